// round 10
// baseline (speedup 1.0000x reference)
#include <cuda_runtime.h>
#include <cstdint>

// PoolingLayer: out[p, f] = max_k features[idx[p,k], f]
// NP=50000, K=32, F=128. features: (100000,128) f32. idx: (50000,32) int32.
//
// R5-R9 established a ~43.5us occupancy-invariant plateau with LDG.128
// gathers. Model: L1tex within-LDG wavefront replay (4 lines/LDG.128 at
// ~2.07 cyc/wf) -> ~8.3 cyc/row/SM floor. This version gathers each 512B row
// as 2x LDG.64 (2 lines each: 1 issue + 1 replay ~3.1 cyc) -> ~6.1 cyc/row.

#define NP_POINTS 50000
#define N_POINTS  100000
#define K_NEIGH   32
#define F_VEC2    64   // 128 floats = 64 float2
#define BATCH     4

#define SZ_FEATURES 12800000   // 100000 * 128 f32
#define SZ_INDICES  1600000    // 50000 * 32

__global__ __launch_bounds__(256, 7)
void pool_max_kernel(const float2* __restrict__ feat,
                     const int* __restrict__ idx,
                     float2* __restrict__ out)
{
    const int gtid = blockIdx.x * blockDim.x + threadIdx.x;
    const int warp = gtid >> 5;
    const int lane = gtid & 31;
    if (warp >= NP_POINTS) return;

    // Coalesced, read-once index load.
    int my_idx = __ldcs(&idx[warp * K_NEIGH + lane]);
    // Clamp: a format surprise becomes rel_err, never an illegal access.
    my_idx = min(max(my_idx, 0), N_POINTS - 1);

    const float NEG_INF = -__int_as_float(0x7f800000);
    float2 mA = make_float2(NEG_INF, NEG_INF);  // row halves: lane, lane+32
    float2 mB = mA;

    #pragma unroll
    for (int kb = 0; kb < K_NEIGH / BATCH; ++kb) {
        // Phase 1: 4 rows x 2 LDG.64 = 8 independent loads in flight.
        float2 a[BATCH], b[BATCH];
        #pragma unroll
        for (int u = 0; u < BATCH; ++u) {
            const int j = __shfl_sync(0xffffffffu, my_idx, kb * BATCH + u);
            const float2* row = feat + (long long)j * F_VEC2;
            a[u] = __ldg(row + lane);
            b[u] = __ldg(row + 32 + lane);
        }
        // Phase 2: pairwise fold, then accumulate.
        float2 a01, a23, b01, b23;
        a01.x = fmaxf(a[0].x, a[1].x);  a23.x = fmaxf(a[2].x, a[3].x);
        a01.y = fmaxf(a[0].y, a[1].y);  a23.y = fmaxf(a[2].y, a[3].y);
        b01.x = fmaxf(b[0].x, b[1].x);  b23.x = fmaxf(b[2].x, b[3].x);
        b01.y = fmaxf(b[0].y, b[1].y);  b23.y = fmaxf(b[2].y, b[3].y);
        mA.x = fmaxf(mA.x, fmaxf(a01.x, a23.x));
        mA.y = fmaxf(mA.y, fmaxf(a01.y, a23.y));
        mB.x = fmaxf(mB.x, fmaxf(b01.x, b23.x));
        mB.y = fmaxf(mB.y, fmaxf(b01.y, b23.y));
    }

    // Write-once output: streaming stores.
    float2* orow = out + (long long)warp * F_VEC2;
    __stcs(orow + lane, mA);
    __stcs(orow + 32 + lane, mB);
}

extern "C" void kernel_launch(void* const* d_in, const int* in_sizes, int n_in,
                              void* d_out, int out_size)
{
    // Resolve inputs by element count (order-independent):
    //   features : 12800000 f32
    //   indices  : 1600000 int32
    const float2* feat = nullptr;
    const int*    idx  = nullptr;
    for (int i = 0; i < n_in; ++i) {
        if (in_sizes[i] == SZ_FEATURES)     feat = (const float2*)d_in[i];
        else if (in_sizes[i] == SZ_INDICES) idx  = (const int*)d_in[i];
    }
    if (!feat) feat = (const float2*)d_in[1];
    if (!idx)  idx  = (const int*)d_in[2];

    float2* out = (float2*)d_out;

    const int total_threads = NP_POINTS * 32;   // one warp per point
    const int block = 256;
    const int grid = (total_threads + block - 1) / block;  // 6250
    pool_max_kernel<<<grid, block>>>(feat, idx, out);
}